// round 11
// baseline (speedup 1.0000x reference)
#include <cuda_runtime.h>

#define DI __device__ __forceinline__
#define NB 64

typedef unsigned long long u64;

// f32x2 packed helpers (two independent fp32 lanes; bitwise == scalar fmaf per lane)
DI u64 PK(float lo, float hi) {
    u64 r; asm("mov.b64 %0, {%1,%2};" : "=l"(r) : "f"(lo), "f"(hi)); return r;
}
DI void UPK(u64 v, float& lo, float& hi) {
    asm("mov.b64 {%0,%1}, %2;" : "=f"(lo), "=f"(hi) : "l"(v));
}
DI u64 FMA2(u64 a, u64 b, u64 c) {
    u64 d; asm("fma.rn.f32x2 %0, %1, %2, %3;" : "=l"(d) : "l"(a), "l"(b), "l"(c)); return d;
}

// ---------------- scratch (static device globals; no allocation) ----------------
__device__ float g_e1[NB*32*128*128];   // e1 out
__device__ float g_e2[NB*64*64*64];     // e2 out
__device__ float g_d1[NB*32*64*64];     // d1 out
__device__ float g_d2[NB*64*128*128];   // d2 out
__device__ float g_enorm[512];

// ---------------- ||e||^2 (sequential, separate mul/add: strict reduce) ----------------
__global__ void k_enorm(const float* __restrict__ emb) {
    int k = threadIdx.x;            // blockDim = 512
    float s = 0.f;
    for (int c = 0; c < 64; c++) {
        float v = emb[k*64 + c];
        s = __fadd_rn(s, __fmul_rn(v, v));
    }
    g_enorm[k] = s;
}

// ---------------- e1: conv 1->32, k4 s2 p1, 256->128, ReLU ----------------
// grid (128=oh, 4=ocg, 64=n), block 128 = ow; 8 oc per thread
__global__ void __launch_bounds__(128) k_e1(const float* __restrict__ x,
                                            const float* __restrict__ w,
                                            const float* __restrict__ b) {
    __shared__ float ws[128];       // 8 oc x 16
    int ow = threadIdx.x;
    int oh = blockIdx.x;
    int ocg = blockIdx.y;
    int n  = blockIdx.z;
    if (ow < 128) { ws[ow] = w[ocg*128 + ow]; }
    __syncthreads();

    const float* xin = x + n*65536;
    float acc[8];
    #pragma unroll
    for (int i = 0; i < 8; i++) acc[i] = 0.f;

    #pragma unroll
    for (int kh = 0; kh < 4; kh++) {
        int ih = oh*2 - 1 + kh;
        if ((unsigned)ih >= 256u) continue;
        const float* row = xin + ih*256;
        #pragma unroll
        for (int kw = 0; kw < 4; kw++) {
            int iw = ow*2 - 1 + kw;
            if ((unsigned)iw >= 256u) continue;
            float xv = __ldg(row + iw);
            #pragma unroll
            for (int i = 0; i < 8; i++)
                acc[i] = fmaf(xv, ws[i*16 + kh*4 + kw], acc[i]);
        }
    }
    #pragma unroll
    for (int i = 0; i < 8; i++) {
        int oc = ocg*8 + i;
        float v = __fadd_rn(acc[i], __ldg(b + oc));
        g_e1[((n*32 + oc)*128 + oh)*128 + ow] = v > 0.f ? v : 0.f;
    }
}

// ---------------- e2: conv 32->64, k4 s2 p1, 128->64, ReLU (f32x2) ----------------
// block 128: tid&7 = owg (8 ow each), tid>>3 = r (16 rows); grid (4, 8=ocg, 64=n)
__global__ void __launch_bounds__(128) k_e2(const float* __restrict__ w,
                                            const float* __restrict__ b) {
    __shared__ float ws[4096];      // 8 oc x 32 ic x 16
    int tid = threadIdx.x;
    int ocg = blockIdx.y;
    int n  = blockIdx.z;
    for (int t = tid; t < 4096; t += 128) ws[t] = w[ocg*4096 + t];
    __syncthreads();

    int owg = tid & 7, r = tid >> 3;
    int oh = blockIdx.x*16 + r;
    int ow0 = owg*8;

    const float* inn = g_e1 + n*(32*16384);
    u64 acc[8][4];
    #pragma unroll
    for (int i = 0; i < 8; i++)
        #pragma unroll
        for (int p = 0; p < 4; p++) acc[i][p] = 0ull;

    #pragma unroll
    for (int kh = 0; kh < 4; kh++) {
        int ih = oh*2 - 1 + kh;
        bool hok = (unsigned)ih < 128u;
        const float* iprow = inn + ih*128;
        #pragma unroll
        for (int kw = 0; kw < 4; kw++) {
            int iwb = ow0*2 - 1 + kw;
            bool ok[8];
            #pragma unroll
            for (int j = 0; j < 8; j++) ok[j] = hok && ((unsigned)(iwb + 2*j) < 128u);
            const float* ip = iprow + iwb;
            int wbase = kh*4 + kw;
            #pragma unroll 4
            for (int ic = 0; ic < 32; ic++) {
                float xv[8];
                #pragma unroll
                for (int j = 0; j < 8; j++)
                    xv[j] = ok[j] ? __ldg(ip + ic*16384 + 2*j) : 0.f;
                u64 xp[4];
                #pragma unroll
                for (int p = 0; p < 4; p++) xp[p] = PK(xv[2*p], xv[2*p+1]);
                #pragma unroll
                for (int i = 0; i < 8; i++) {
                    float wv = ws[i*512 + ic*16 + wbase];
                    u64 wp = PK(wv, wv);
                    #pragma unroll
                    for (int p = 0; p < 4; p++)
                        acc[i][p] = FMA2(xp[p], wp, acc[i][p]);
                }
            }
        }
    }
    #pragma unroll
    for (int i = 0; i < 8; i++) {
        int oc = ocg*8 + i;
        float bb = __ldg(b + oc);
        float* op = g_e2 + ((n*64 + oc)*64 + oh)*64 + ow0;
        #pragma unroll
        for (int p = 0; p < 4; p++) {
            float v0, v1; UPK(acc[i][p], v0, v1);
            v0 = __fadd_rn(v0, bb); v1 = __fadd_rn(v1, bb);
            op[2*p]   = v0 > 0.f ? v0 : 0.f;
            op[2*p+1] = v1 > 0.f ? v1 : 0.f;
        }
    }
}

// ---------------- e3: conv 64->64, k3 s1 p1, 64x64, ReLU (f32x2) ----------------
// block 128: tid&7 = owg (8 ow each), tid>>3 = r (16 rows); grid (4, 8=ocg, 64=n)
__global__ void __launch_bounds__(128) k_e3(const float* __restrict__ w,
                                            const float* __restrict__ b,
                                            float* __restrict__ ze) {
    __shared__ float ws[4608];      // 8 oc x 64 ic x 9
    int tid = threadIdx.x;
    int ocg = blockIdx.y;
    int n  = blockIdx.z;
    for (int t = tid; t < 4608; t += 128) ws[t] = w[ocg*4608 + t];
    __syncthreads();

    int owg = tid & 7, r = tid >> 3;
    int oh = blockIdx.x*16 + r;
    int ow0 = owg*8;

    const float* inn = g_e2 + n*(64*4096);
    u64 acc[8][4];
    #pragma unroll
    for (int i = 0; i < 8; i++)
        #pragma unroll
        for (int p = 0; p < 4; p++) acc[i][p] = 0ull;

    #pragma unroll
    for (int kh = 0; kh < 3; kh++) {
        int ih = oh - 1 + kh;
        bool hok = (unsigned)ih < 64u;
        const float* iprow = inn + ih*64;
        #pragma unroll
        for (int kw = 0; kw < 3; kw++) {
            int iwb = ow0 - 1 + kw;
            bool ok[8];
            #pragma unroll
            for (int j = 0; j < 8; j++) ok[j] = hok && ((unsigned)(iwb + j) < 64u);
            const float* ip = iprow + iwb;
            int wbase = kh*3 + kw;
            #pragma unroll 4
            for (int ic = 0; ic < 64; ic++) {
                float xv[8];
                #pragma unroll
                for (int j = 0; j < 8; j++)
                    xv[j] = ok[j] ? __ldg(ip + ic*4096 + j) : 0.f;
                u64 xp[4];
                #pragma unroll
                for (int p = 0; p < 4; p++) xp[p] = PK(xv[2*p], xv[2*p+1]);
                #pragma unroll
                for (int i = 0; i < 8; i++) {
                    float wv = ws[i*576 + ic*9 + wbase];
                    u64 wp = PK(wv, wv);
                    #pragma unroll
                    for (int p = 0; p < 4; p++)
                        acc[i][p] = FMA2(xp[p], wp, acc[i][p]);
                }
            }
        }
    }
    #pragma unroll
    for (int i = 0; i < 8; i++) {
        int oc = ocg*8 + i;
        float bb = __ldg(b + oc);
        float* op = ze + ((n*64 + oc)*64 + oh)*64 + ow0;
        #pragma unroll
        for (int p = 0; p < 4; p++) {
            float v0, v1; UPK(acc[i][p], v0, v1);
            v0 = __fadd_rn(v0, bb); v1 = __fadd_rn(v1, bb);
            op[2*p]   = v0 > 0.f ? v0 : 0.f;
            op[2*p+1] = v1 > 0.f ? v1 : 0.f;
        }
    }
}

// ---------------- VQ: argmin over 512 codes, write zq (f32x2, dup codebook) ----------------
// dist = (||z||^2 - 2*(z.e)) + ||e||^2, each lane of dp an exact ascending-c fmaf chain.
// block 128 thr, 2 locations/thread (packed as f32x2 lanes); grid 1024; 8 chunks of 64 codes.
__global__ void __launch_bounds__(128) k_vq(const float* __restrict__ ze,
                                            const float* __restrict__ emb,
                                            float* __restrict__ zq) {
    __shared__ ulonglong2 sdup[64*32];   // 64 codes x 64 ch, each ch duplicated (32KB)
    __shared__ float      sn[64];
    int tid = threadIdx.x;
    int loc0 = blockIdx.x*256 + tid;
    int loc1 = loc0 + 128;
    int n0 = loc0 >> 12, hw0 = loc0 & 4095;
    int n1 = loc1 >> 12, hw1 = loc1 & 4095;

    float z0[64], z1[64];
    const float* p0 = ze + n0*(64*4096) + hw0;
    const float* p1 = ze + n1*(64*4096) + hw1;
    #pragma unroll
    for (int c = 0; c < 64; c++) {
        z0[c] = __ldg(p0 + c*4096);
        z1[c] = __ldg(p1 + c*4096);
    }
    float A0 = 0.f, A1 = 0.f;
    #pragma unroll
    for (int c = 0; c < 64; c++) {
        A0 = __fadd_rn(A0, __fmul_rn(z0[c], z0[c]));
        A1 = __fadd_rn(A1, __fmul_rn(z1[c], z1[c]));
    }
    u64 zp[64];
    #pragma unroll
    for (int c = 0; c < 64; c++) zp[c] = PK(z0[c], z1[c]);

    float best0 = 3.4e38f, best1 = 3.4e38f;
    int bi0 = 0, bi1 = 0;
    float2* f2 = (float2*)sdup;
    for (int kc = 0; kc < 8; kc++) {
        __syncthreads();
        const float* src = emb + kc*64*64;
        for (int t = tid; t < 4096; t += 128) {
            float v = __ldg(src + t);
            f2[t] = make_float2(v, v);
        }
        if (tid < 64) sn[tid] = g_enorm[kc*64 + tid];
        __syncthreads();

        for (int kk = 0; kk < 64; kk++) {
            const ulonglong2* ep = sdup + kk*32;
            u64 dp = 0ull;
            #pragma unroll
            for (int q = 0; q < 32; q++) {
                ulonglong2 e2 = ep[q];
                dp = FMA2(zp[2*q],   e2.x, dp);
                dp = FMA2(zp[2*q+1], e2.y, dp);
            }
            float d0, d1; UPK(dp, d0, d1);
            float nn = sn[kk];
            float dist0 = __fadd_rn(__fsub_rn(A0, __fmul_rn(2.0f, d0)), nn);
            float dist1 = __fadd_rn(__fsub_rn(A1, __fmul_rn(2.0f, d1)), nn);
            int k = kc*64 + kk;
            if (dist0 < best0) { best0 = dist0; bi0 = k; }
            if (dist1 < best1) { best1 = dist1; bi1 = k; }
        }
    }
    float* q0 = zq + n0*(64*4096) + hw0;
    float* q1 = zq + n1*(64*4096) + hw1;
    const float* e0 = emb + bi0*64;
    const float* e1 = emb + bi1*64;
    #pragma unroll
    for (int c = 0; c < 64; c++) {
        q0[c*4096] = __ldg(e0 + c);
        q1[c*4096] = __ldg(e1 + c);
    }
}

// ---------------- d1: convT 64->32 k3 s1 p1 == conv with flipped w (f32x2) ----------------
// block 64 thr: tid&3 = spg (4 x 16), tid>>2 = row (16 rows); grid (4, N, 4)
__global__ void __launch_bounds__(64) k_d1(const float* __restrict__ zq,
                                           const float* __restrict__ w,
                                           const float* __restrict__ b) {
    __shared__ float ws[8*64*9];
    int tid = threadIdx.x;
    int ocg = blockIdx.z;
    for (int t = tid; t < 8*64*9; t += 64) {
        int i  = t / 576;
        int rm = t - i*576;
        int ic = rm / 9;
        int kk = rm - ic*9;
        int kh = kk / 3, kw = kk - kh*3;
        int oc = ocg*8 + i;
        ws[t] = w[((ic*32 + oc)*3 + (2 - kh))*3 + (2 - kw)];  // (in,out,kh,kw) flipped
    }
    __syncthreads();

    int spg = tid & 3, r = tid >> 2;
    int n = blockIdx.y;
    int oh = blockIdx.x*16 + r;
    int ow0 = spg*16;

    u64 acc[8][8];   // 8 oc x 8 pairs (16 ow)
    #pragma unroll
    for (int i = 0; i < 8; i++)
        #pragma unroll
        for (int m = 0; m < 8; m++) acc[i][m] = 0ull;

    const float* inn = zq + n*(64*4096);
    for (int ic = 0; ic < 64; ic++) {
        const float* ip = inn + ic*4096;
        #pragma unroll
        for (int kh = 0; kh < 3; kh++) {
            int ih = oh - 1 + kh;
            if ((unsigned)ih >= 64u) continue;
            float rv[18];
            const float* row = ip + ih*64;
            #pragma unroll
            for (int t = 0; t < 18; t++) {
                int iw = ow0 - 1 + t;
                rv[t] = ((unsigned)iw < 64u) ? __ldg(row + iw) : 0.f;
            }
            #pragma unroll
            for (int kw = 0; kw < 3; kw++) {
                u64 ap[8];
                #pragma unroll
                for (int m = 0; m < 8; m++) ap[m] = PK(rv[2*m + kw], rv[2*m + 1 + kw]);
                #pragma unroll
                for (int i = 0; i < 8; i++) {
                    float wv = ws[(i*64 + ic)*9 + kh*3 + kw];
                    u64 wp = PK(wv, wv);
                    #pragma unroll
                    for (int m = 0; m < 8; m++)
                        acc[i][m] = FMA2(ap[m], wp, acc[i][m]);
                }
            }
        }
    }
    #pragma unroll
    for (int i = 0; i < 8; i++) {
        int oc = ocg*8 + i;
        float bb = __ldg(b + oc);
        float* op = g_d1 + ((n*32 + oc)*64 + oh)*64 + ow0;
        #pragma unroll
        for (int m = 0; m < 8; m++) {
            float v0, v1; UPK(acc[i][m], v0, v1);
            v0 += bb; v1 += bb;
            op[2*m]   = v0 > 0.f ? v0 : 0.f;
            op[2*m+1] = v1 > 0.f ? v1 : 0.f;
        }
    }
}

// ---------------- d2: convT 32->64, k4 s2 p1, 64->128, ReLU (f32x2) ----------------
// Output pair lanes: lane0 = j=2m (q==1 taps: w01,w03,w21,w23; s=m+1),
//                    lane1 = j=2m+1 (q==0 taps: w00,w02,w20,w22; s=m+2).
// block 64: tid&3 = spg (4 x 32), tid>>2 = row (16); grid (8, N, 16)
__global__ void __launch_bounds__(64) k_d2(const float* __restrict__ w,
                                           const float* __restrict__ b) {
    __shared__ float ws[2048];   // [ic][i(4)][16]
    int tid = threadIdx.x;
    int ocg = blockIdx.z;
    for (int t = tid; t < 2048; t += 64) {
        int ic = t >> 6;
        int i  = (t >> 4) & 3;
        int kk = t & 15;
        ws[t] = w[(ic*64 + ocg*4 + i)*16 + kk];
    }
    __syncthreads();

    int spg = tid & 3, r = tid >> 2;
    int n = blockIdx.y;
    int oh = blockIdx.x*16 + r;
    int ow0 = spg*32;

    u64 acc[4][16];   // 4 oc x 16 pairs (32 ow)
    #pragma unroll
    for (int i = 0; i < 4; i++)
        #pragma unroll
        for (int m = 0; m < 16; m++) acc[i][m] = 0ull;

    int p = (oh + 1) & 1;
    int ih1 = (oh + 1 - p) >> 1;
    int ih2 = ih1 - 1;
    bool h1ok = (unsigned)ih1 < 64u, h2ok = (unsigned)ih2 < 64u;
    const float* inn = g_d1 + n*(32*4096);

    for (int ic = 0; ic < 32; ic++) {
        const float* ip = inn + ic*4096;
        float rv1[18], rv2[18];
        int iwb = (ow0 >> 1) - 1;
        #pragma unroll
        for (int t = 0; t < 18; t++) {
            int iw = iwb + t;
            bool wok = (unsigned)iw < 64u;
            rv1[t] = (wok && h1ok) ? __ldg(ip + ih1*64 + iw) : 0.f;
            rv2[t] = (wok && h2ok) ? __ldg(ip + ih2*64 + iw) : 0.f;
        }
        const float* wp = &ws[ic*64];
        u64 wA[4], wB[4], wC[4], wD[4];
        #pragma unroll
        for (int i = 0; i < 4; i++) {
            const float* wpi = wp + i*16;
            wA[i] = PK(wpi[p*4 + 1],     wpi[p*4 + 0]);      // (w01, w00)
            wB[i] = PK(wpi[p*4 + 3],     wpi[p*4 + 2]);      // (w03, w02)
            wC[i] = PK(wpi[(p+2)*4 + 1], wpi[(p+2)*4 + 0]);  // (w21, w20)
            wD[i] = PK(wpi[(p+2)*4 + 3], wpi[(p+2)*4 + 2]);  // (w23, w22)
        }
        #pragma unroll
        for (int m = 0; m < 16; m++) {
            u64 a1a = PK(rv1[m+1], rv1[m+2]);
            u64 a1b = PK(rv1[m],   rv1[m+1]);
            u64 a2a = PK(rv2[m+1], rv2[m+2]);
            u64 a2b = PK(rv2[m],   rv2[m+1]);
            #pragma unroll
            for (int i = 0; i < 4; i++) {
                u64 v = acc[i][m];
                v = FMA2(a1a, wA[i], v);
                v = FMA2(a1b, wB[i], v);
                v = FMA2(a2a, wC[i], v);
                v = FMA2(a2b, wD[i], v);
                acc[i][m] = v;
            }
        }
    }
    #pragma unroll
    for (int i = 0; i < 4; i++) {
        int oc = ocg*4 + i;
        float bb = __ldg(b + oc);
        float* op = g_d2 + ((n*64 + oc)*128 + oh)*128 + ow0;
        #pragma unroll
        for (int m = 0; m < 16; m++) {
            float v0, v1; UPK(acc[i][m], v0, v1);
            v0 += bb; v1 += bb;
            op[2*m]   = v0 > 0.f ? v0 : 0.f;
            op[2*m+1] = v1 > 0.f ? v1 : 0.f;
        }
    }
}

// ---------------- d3: convT 64->1, k4 s2 p1, 128->256, no ReLU ----------------
// block 64: tid&15 = owg (16 x 16), tid>>4 = ohg (4 x 4 rows); grid (16, N)
__global__ void __launch_bounds__(64) k_d3(const float* __restrict__ w,
                                           const float* __restrict__ b,
                                           float* __restrict__ out) {
    __shared__ float ws[1024];
    int tid = threadIdx.x;
    for (int t = tid; t < 1024; t += 64) ws[t] = w[t];
    __syncthreads();

    int owg = tid & 15, ohg = tid >> 4;
    int n = blockIdx.y;
    int ob = blockIdx.x*16 + ohg*4;
    int ow0 = owg*16;

    float acc[4][16];
    #pragma unroll
    for (int i = 0; i < 4; i++)
        #pragma unroll
        for (int j = 0; j < 16; j++) acc[i][j] = 0.f;

    int ihb = (ob >> 1) - 1;
    int iwb = (ow0 >> 1) - 1;
    const float* inn = g_d2 + n*(64*16384);

    for (int ic = 0; ic < 64; ic++) {
        const float* ip = inn + ic*16384;
        float rv[4][10];
        #pragma unroll
        for (int rr = 0; rr < 4; rr++) {
            int ih = ihb + rr;
            bool hok = (unsigned)ih < 128u;
            const float* row = ip + ih*128;
            #pragma unroll
            for (int t = 0; t < 10; t++) {
                int iw = iwb + t;
                rv[rr][t] = (hok && (unsigned)iw < 128u) ? __ldg(row + iw) : 0.f;
            }
        }
        float wr[16];
        #pragma unroll
        for (int t = 0; t < 16; t++) wr[t] = ws[ic*16 + t];

        #pragma unroll
        for (int rr = 0; rr < 4; rr++) {
            const int pp = (rr + 1) & 1;
            const int rel1 = ((rr + 1) >> 1) + 1;
            const int rel2 = rel1 - 1;
            #pragma unroll
            for (int j = 0; j < 16; j++) {
                const int q = (j + 1) & 1;
                const int s = ((j + 1) >> 1) + 1;
                float v = acc[rr][j];
                v = fmaf(rv[rel1][s],   wr[pp*4 + q],       v);
                v = fmaf(rv[rel1][s-1], wr[pp*4 + q + 2],   v);
                v = fmaf(rv[rel2][s],   wr[(pp+2)*4 + q],   v);
                v = fmaf(rv[rel2][s-1], wr[(pp+2)*4 + q+2], v);
                acc[rr][j] = v;
            }
        }
    }
    float bb = __ldg(b);
    #pragma unroll
    for (int rr = 0; rr < 4; rr++) {
        float* op = out + n*65536 + (ob + rr)*256 + ow0;
        #pragma unroll
        for (int j = 0; j < 16; j++) op[j] = acc[rr][j] + bb;
    }
}

// ---------------- launch ----------------
extern "C" void kernel_launch(void* const* d_in, const int* in_sizes, int n_in,
                              void* d_out, int out_size) {
    const float* x   = (const float*)d_in[0];
    const float* e1w = (const float*)d_in[1];  const float* e1b = (const float*)d_in[2];
    const float* e2w = (const float*)d_in[3];  const float* e2b = (const float*)d_in[4];
    const float* e3w = (const float*)d_in[5];  const float* e3b = (const float*)d_in[6];
    const float* emb = (const float*)d_in[7];
    const float* d1w = (const float*)d_in[8];  const float* d1b = (const float*)d_in[9];
    const float* d2w = (const float*)d_in[10]; const float* d2b = (const float*)d_in[11];
    const float* d3w = (const float*)d_in[12]; const float* d3b = (const float*)d_in[13];

    float* out  = (float*)d_out;
    float* xhat = out;                          // 64*1*256*256   = 4194304
    float* ze   = out + 4194304;                // 64*64*64*64    = 16777216
    float* zq   = out + 4194304 + 16777216;     // 64*64*64*64

    k_enorm<<<1, 512>>>(emb);
    k_e1<<<dim3(128, 4, NB), 128>>>(x, e1w, e1b);
    k_e2<<<dim3(4, 8, NB), 128>>>(e2w, e2b);
    k_e3<<<dim3(4, 8, NB), 128>>>(e3w, e3b, ze);
    k_vq<<<1024, 128>>>(ze, emb, zq);
    k_d1<<<dim3(4, NB, 4), 64>>>(zq, d1w, d1b);
    k_d2<<<dim3(8, NB, 16), 64>>>(d2w, d2b);
    k_d3<<<dim3(16, NB), 64>>>(d3w, d3b, xhat);
}

// round 17
// speedup vs baseline: 1.5067x; 1.5067x over previous
#include <cuda_runtime.h>

#define DI __device__ __forceinline__
#define NB 64

typedef unsigned long long u64;

// f32x2 packed helpers (two independent fp32 lanes; bit-exact per lane — verified R11)
DI u64 PK(float lo, float hi) {
    u64 r; asm("mov.b64 %0, {%1,%2};" : "=l"(r) : "f"(lo), "f"(hi)); return r;
}
DI void UPK(u64 v, float& lo, float& hi) {
    asm("mov.b64 {%0,%1}, %2;" : "=f"(lo), "=f"(hi) : "l"(v));
}
DI u64 FMA2(u64 a, u64 b, u64 c) {
    u64 d; asm("fma.rn.f32x2 %0, %1, %2, %3;" : "=l"(d) : "l"(a), "l"(b), "l"(c)); return d;
}

// ---------------- scratch (static device globals; no allocation) ----------------
__device__ float g_e1[NB*32*128*128];   // e1 out
__device__ float g_e2[NB*64*64*64];     // e2 out
__device__ float g_d1[NB*32*64*64];     // d1 out
__device__ float g_d2[NB*64*128*128];   // d2 out
__device__ float g_enorm[512];

// ---------------- ||e||^2 (sequential, separate mul/add: strict reduce) ----------------
__global__ void k_enorm(const float* __restrict__ emb) {
    int k = threadIdx.x;            // blockDim = 512
    float s = 0.f;
    for (int c = 0; c < 64; c++) {
        float v = emb[k*64 + c];
        s = __fadd_rn(s, __fmul_rn(v, v));
    }
    g_enorm[k] = s;
}

// ---------------- e1: conv 1->32, k4 s2 p1, 256->128, ReLU ----------------
// grid (128=oh, 4=ocg, 64=n), block 128 = ow; 8 oc per thread
__global__ void __launch_bounds__(128) k_e1(const float* __restrict__ x,
                                            const float* __restrict__ w,
                                            const float* __restrict__ b) {
    __shared__ float ws[128];       // 8 oc x 16
    int ow = threadIdx.x;
    int oh = blockIdx.x;
    int ocg = blockIdx.y;
    int n  = blockIdx.z;
    if (ow < 128) { ws[ow] = w[ocg*128 + ow]; }
    __syncthreads();

    const float* xin = x + n*65536;
    float acc[8];
    #pragma unroll
    for (int i = 0; i < 8; i++) acc[i] = 0.f;

    #pragma unroll
    for (int kh = 0; kh < 4; kh++) {
        int ih = oh*2 - 1 + kh;
        if ((unsigned)ih >= 256u) continue;
        const float* row = xin + ih*256;
        #pragma unroll
        for (int kw = 0; kw < 4; kw++) {
            int iw = ow*2 - 1 + kw;
            if ((unsigned)iw >= 256u) continue;
            float xv = __ldg(row + iw);
            #pragma unroll
            for (int i = 0; i < 8; i++)
                acc[i] = fmaf(xv, ws[i*16 + kh*4 + kw], acc[i]);
        }
    }
    #pragma unroll
    for (int i = 0; i < 8; i++) {
        int oc = ocg*8 + i;
        float v = __fadd_rn(acc[i], __ldg(b + oc));
        g_e1[((n*32 + oc)*128 + oh)*128 + ow] = v > 0.f ? v : 0.f;
    }
}

// ---------------- e2: conv 32->64, k4 s2 p1, 128->64, ReLU (f32x2, coalesced) ----------------
// chain per output: (kh, kw, ic) ic-innermost; lane s handles ow pair (s, s+32).
// block 256: s=tid&31, r=tid>>5 (8 rows); grid (8 row-tiles, 8=ocg, 64=n)
__global__ void __launch_bounds__(256) k_e2(const float* __restrict__ w,
                                            const float* __restrict__ b) {
    __shared__ ulonglong2 wsd[16*32*4];   // [kk][ic][oc-pair] duplicated float2, 32KB
    float2* wf = (float2*)wsd;
    int tid = threadIdx.x;
    int ocg = blockIdx.y;
    int n  = blockIdx.z;
    for (int t = tid; t < 16*32*8; t += 256) {
        int i  = t & 7;
        int ic = (t >> 3) & 31;
        int kk = t >> 8;
        float v = w[((ocg*8 + i)*32 + ic)*16 + kk];
        wf[(kk*32 + ic)*8 + i] = make_float2(v, v);
    }
    __syncthreads();

    int s = tid & 31, r = tid >> 5;
    int oh = blockIdx.x*8 + r;

    const float* inn = g_e1 + n*(32*16384);
    u64 acc[8];
    #pragma unroll
    for (int i = 0; i < 8; i++) acc[i] = 0ull;

    #pragma unroll
    for (int kh = 0; kh < 4; kh++) {
        int ih = oh*2 - 1 + kh;
        bool hok = (unsigned)ih < 128u;
        const float* prow = inn + ih*128;
        #pragma unroll
        for (int kw = 0; kw < 4; kw++) {
            int iw0 = 2*s - 1 + kw;        // ow = s
            int iw1 = 2*s + 63 + kw;       // ow = s+32
            bool ok0 = hok && ((unsigned)iw0 < 128u);
            bool ok1 = hok && (iw1 < 128);
            const ulonglong2* wrow = wsd + (kh*4 + kw)*128;   // 32 ic x 4 pairs
            #pragma unroll 4
            for (int ic = 0; ic < 32; ic++) {
                float x0 = ok0 ? __ldg(prow + ic*16384 + iw0) : 0.f;
                float x1 = ok1 ? __ldg(prow + ic*16384 + iw1) : 0.f;
                u64 xp = PK(x0, x1);
                ulonglong2 w0 = wrow[ic*4+0];
                ulonglong2 w1 = wrow[ic*4+1];
                ulonglong2 w2 = wrow[ic*4+2];
                ulonglong2 w3 = wrow[ic*4+3];
                acc[0] = FMA2(xp, w0.x, acc[0]); acc[1] = FMA2(xp, w0.y, acc[1]);
                acc[2] = FMA2(xp, w1.x, acc[2]); acc[3] = FMA2(xp, w1.y, acc[3]);
                acc[4] = FMA2(xp, w2.x, acc[4]); acc[5] = FMA2(xp, w2.y, acc[5]);
                acc[6] = FMA2(xp, w3.x, acc[6]); acc[7] = FMA2(xp, w3.y, acc[7]);
            }
        }
    }
    #pragma unroll
    for (int i = 0; i < 8; i++) {
        int oc = ocg*8 + i;
        float bb = __ldg(b + oc);
        float v0, v1; UPK(acc[i], v0, v1);
        v0 = __fadd_rn(v0, bb); v1 = __fadd_rn(v1, bb);
        float* op = g_e2 + ((n*64 + oc)*64 + oh)*64;
        op[s]      = v0 > 0.f ? v0 : 0.f;
        op[s + 32] = v1 > 0.f ? v1 : 0.f;
    }
}

// ---------------- e3: conv 64->64, k3 s1 p1, 64x64, ReLU (f32x2, coalesced) ----------------
// chain per output: (kh, kw, ic) ic-innermost; lane s handles ow pair (s, s+32).
// block 256: s=tid&31, r=tid>>5 (8 rows); grid (8 row-tiles, 8=ocg, 64=n)
__global__ void __launch_bounds__(256) k_e3(const float* __restrict__ w,
                                            const float* __restrict__ b,
                                            float* __restrict__ ze) {
    __shared__ ulonglong2 wsd[9*64*4];    // [kk][ic][oc-pair] duplicated float2, 36KB
    float2* wf = (float2*)wsd;
    int tid = threadIdx.x;
    int ocg = blockIdx.y;
    int n  = blockIdx.z;
    for (int t = tid; t < 9*64*8; t += 256) {
        int i  = t & 7;
        int ic = (t >> 3) & 63;
        int kk = t >> 9;
        float v = w[(ocg*8 + i)*576 + ic*9 + kk];
        wf[(kk*64 + ic)*8 + i] = make_float2(v, v);
    }
    __syncthreads();

    int s = tid & 31, r = tid >> 5;
    int oh = blockIdx.x*8 + r;

    const float* inn = g_e2 + n*(64*4096);
    u64 acc[8];
    #pragma unroll
    for (int i = 0; i < 8; i++) acc[i] = 0ull;

    #pragma unroll
    for (int kh = 0; kh < 3; kh++) {
        int ih = oh - 1 + kh;
        bool hok = (unsigned)ih < 64u;
        const float* prow = inn + ih*64;
        #pragma unroll
        for (int kw = 0; kw < 3; kw++) {
            int iw0 = s - 1 + kw;          // ow = s
            int iw1 = s + 31 + kw;         // ow = s+32
            bool ok0 = hok && ((unsigned)iw0 < 64u);
            bool ok1 = hok && (iw1 < 64);
            const ulonglong2* wrow = wsd + (kh*3 + kw)*256;   // 64 ic x 4 pairs
            #pragma unroll 4
            for (int ic = 0; ic < 64; ic++) {
                float x0 = ok0 ? __ldg(prow + ic*4096 + iw0) : 0.f;
                float x1 = ok1 ? __ldg(prow + ic*4096 + iw1) : 0.f;
                u64 xp = PK(x0, x1);
                ulonglong2 w0 = wrow[ic*4+0];
                ulonglong2 w1 = wrow[ic*4+1];
                ulonglong2 w2 = wrow[ic*4+2];
                ulonglong2 w3 = wrow[ic*4+3];
                acc[0] = FMA2(xp, w0.x, acc[0]); acc[1] = FMA2(xp, w0.y, acc[1]);
                acc[2] = FMA2(xp, w1.x, acc[2]); acc[3] = FMA2(xp, w1.y, acc[3]);
                acc[4] = FMA2(xp, w2.x, acc[4]); acc[5] = FMA2(xp, w2.y, acc[5]);
                acc[6] = FMA2(xp, w3.x, acc[6]); acc[7] = FMA2(xp, w3.y, acc[7]);
            }
        }
    }
    #pragma unroll
    for (int i = 0; i < 8; i++) {
        int oc = ocg*8 + i;
        float bb = __ldg(b + oc);
        float v0, v1; UPK(acc[i], v0, v1);
        v0 = __fadd_rn(v0, bb); v1 = __fadd_rn(v1, bb);
        float* op = ze + ((n*64 + oc)*64 + oh)*64;
        op[s]      = v0 > 0.f ? v0 : 0.f;
        op[s + 32] = v1 > 0.f ? v1 : 0.f;
    }
}

// ---------------- VQ: argmin over 512 codes, write zq (R5 form) ----------------
__global__ void __launch_bounds__(128) k_vq(const float* __restrict__ ze,
                                            const float* __restrict__ emb,
                                            float* __restrict__ zq) {
    __shared__ float4 se4[128*16];   // 128 codes x 64 floats
    __shared__ float  sn[128];
    int tid = threadIdx.x;
    int loc0 = blockIdx.x*256 + tid;
    int loc1 = loc0 + 128;
    int n0 = loc0 >> 12, hw0 = loc0 & 4095;
    int n1 = loc1 >> 12, hw1 = loc1 & 4095;

    float z0[64], z1[64];
    const float* p0 = ze + n0*(64*4096) + hw0;
    const float* p1 = ze + n1*(64*4096) + hw1;
    #pragma unroll
    for (int c = 0; c < 64; c++) {
        z0[c] = __ldg(p0 + c*4096);
        z1[c] = __ldg(p1 + c*4096);
    }
    float A0 = 0.f, A1 = 0.f;
    #pragma unroll
    for (int c = 0; c < 64; c++) {
        A0 = __fadd_rn(A0, __fmul_rn(z0[c], z0[c]));
        A1 = __fadd_rn(A1, __fmul_rn(z1[c], z1[c]));
    }

    float best0 = 3.4e38f, best1 = 3.4e38f;
    int bi0 = 0, bi1 = 0;
    for (int kc = 0; kc < 4; kc++) {
        __syncthreads();
        const float4* src = (const float4*)(emb + kc*128*64);
        for (int t = tid; t < 2048; t += 128) se4[t] = __ldg(src + t);
        sn[tid] = g_enorm[kc*128 + tid];
        __syncthreads();

        for (int kk = 0; kk < 128; kk++) {
            float d0 = 0.f, d1 = 0.f;
            #pragma unroll
            for (int c4 = 0; c4 < 16; c4++) {
                float4 e = se4[kk*16 + c4];
                d0 = fmaf(z0[4*c4+0], e.x, d0); d1 = fmaf(z1[4*c4+0], e.x, d1);
                d0 = fmaf(z0[4*c4+1], e.y, d0); d1 = fmaf(z1[4*c4+1], e.y, d1);
                d0 = fmaf(z0[4*c4+2], e.z, d0); d1 = fmaf(z1[4*c4+2], e.z, d1);
                d0 = fmaf(z0[4*c4+3], e.w, d0); d1 = fmaf(z1[4*c4+3], e.w, d1);
            }
            float nn = sn[kk];
            float dist0 = __fadd_rn(__fsub_rn(A0, __fmul_rn(2.0f, d0)), nn);
            float dist1 = __fadd_rn(__fsub_rn(A1, __fmul_rn(2.0f, d1)), nn);
            int k = kc*128 + kk;
            if (dist0 < best0) { best0 = dist0; bi0 = k; }
            if (dist1 < best1) { best1 = dist1; bi1 = k; }
        }
    }
    float* q0 = zq + n0*(64*4096) + hw0;
    float* q1 = zq + n1*(64*4096) + hw1;
    const float* e0 = emb + bi0*64;
    const float* e1 = emb + bi1*64;
    #pragma unroll
    for (int c = 0; c < 64; c++) {
        q0[c*4096] = __ldg(e0 + c);
        q1[c*4096] = __ldg(e1 + c);
    }
}

// ---------------- d1: convT 64->32 k3 s1 p1 == conv with flipped w (R5 form) ----------------
// block 64 thr: tid&3 = spg (4 x 16), tid>>2 = row (16 rows); grid (4, N, 4)
__global__ void __launch_bounds__(64) k_d1(const float* __restrict__ zq,
                                           const float* __restrict__ w,
                                           const float* __restrict__ b) {
    __shared__ float ws[8*64*9];
    int tid = threadIdx.x;
    int ocg = blockIdx.z;
    for (int t = tid; t < 8*64*9; t += 64) {
        int i  = t / 576;
        int rm = t - i*576;
        int ic = rm / 9;
        int kk = rm - ic*9;
        int kh = kk / 3, kw = kk - kh*3;
        int oc = ocg*8 + i;
        ws[t] = w[((ic*32 + oc)*3 + (2 - kh))*3 + (2 - kw)];  // (in,out,kh,kw) flipped
    }
    __syncthreads();

    int spg = tid & 3, r = tid >> 2;
    int n = blockIdx.y;
    int oh = blockIdx.x*16 + r;
    int ow0 = spg*16;

    float acc[8][16];
    #pragma unroll
    for (int i = 0; i < 8; i++)
        #pragma unroll
        for (int j = 0; j < 16; j++) acc[i][j] = 0.f;

    const float* inn = zq + n*(64*4096);
    for (int ic = 0; ic < 64; ic++) {
        const float* ip = inn + ic*4096;
        for (int kh = 0; kh < 3; kh++) {
            int ih = oh - 1 + kh;
            if ((unsigned)ih >= 64u) continue;
            float rv[18];
            const float* row = ip + ih*64;
            #pragma unroll
            for (int t = 0; t < 18; t++) {
                int iw = ow0 - 1 + t;
                rv[t] = ((unsigned)iw < 64u) ? __ldg(row + iw) : 0.f;
            }
            #pragma unroll
            for (int kw = 0; kw < 3; kw++)
                #pragma unroll
                for (int i = 0; i < 8; i++) {
                    float wv = ws[(i*64 + ic)*9 + kh*3 + kw];
                    #pragma unroll
                    for (int j = 0; j < 16; j++)
                        acc[i][j] = fmaf(rv[j + kw], wv, acc[i][j]);
                }
        }
    }
    #pragma unroll
    for (int i = 0; i < 8; i++) {
        int oc = ocg*8 + i;
        float bb = __ldg(b + oc);
        float* op = g_d1 + ((n*32 + oc)*64 + oh)*64 + ow0;
        #pragma unroll
        for (int j = 0; j < 16; j++) {
            float v = acc[i][j] + bb;
            op[j] = v > 0.f ? v : 0.f;
        }
    }
}

// ---------------- d2: convT 32->64, k4 s2 p1, 64->128, ReLU (R5 form) ----------------
// block 64: tid&3 = spg (4 x 32), tid>>2 = row (16); grid (8, N, 16)
__global__ void __launch_bounds__(64) k_d2(const float* __restrict__ w,
                                           const float* __restrict__ b) {
    __shared__ float ws[2048];   // [ic][i(4)][16]
    int tid = threadIdx.x;
    int ocg = blockIdx.z;
    for (int t = tid; t < 2048; t += 64) {
        int ic = t >> 6;
        int i  = (t >> 4) & 3;
        int kk = t & 15;
        ws[t] = w[(ic*64 + ocg*4 + i)*16 + kk];
    }
    __syncthreads();

    int spg = tid & 3, r = tid >> 2;
    int n = blockIdx.y;
    int oh = blockIdx.x*16 + r;
    int ow0 = spg*32;

    float acc[4][32];
    #pragma unroll
    for (int i = 0; i < 4; i++)
        #pragma unroll
        for (int j = 0; j < 32; j++) acc[i][j] = 0.f;

    int p = (oh + 1) & 1;
    int ih1 = (oh + 1 - p) >> 1;
    int ih2 = ih1 - 1;
    bool h1ok = (unsigned)ih1 < 64u, h2ok = (unsigned)ih2 < 64u;
    const float* inn = g_d1 + n*(32*4096);

    for (int ic = 0; ic < 32; ic++) {
        const float* ip = inn + ic*4096;
        float rv1[18], rv2[18];
        int iwb = (ow0 >> 1) - 1;
        #pragma unroll
        for (int t = 0; t < 18; t++) {
            int iw = iwb + t;
            bool wok = (unsigned)iw < 64u;
            rv1[t] = (wok && h1ok) ? __ldg(ip + ih1*64 + iw) : 0.f;
            rv2[t] = (wok && h2ok) ? __ldg(ip + ih2*64 + iw) : 0.f;
        }
        const float* wp = &ws[ic*64];
        #pragma unroll
        for (int i = 0; i < 4; i++) {
            const float* wpi = wp + i*16;
            float w00 = wpi[p*4 + 0], w02 = wpi[p*4 + 2];
            float w01 = wpi[p*4 + 1], w03 = wpi[p*4 + 3];
            float w20 = wpi[(p+2)*4 + 0], w22 = wpi[(p+2)*4 + 2];
            float w21 = wpi[(p+2)*4 + 1], w23 = wpi[(p+2)*4 + 3];
            #pragma unroll
            for (int j = 0; j < 32; j++) {
                const int q = (j + 1) & 1;
                const int s = ((j + 1) >> 1) + 1;
                float v = acc[i][j];
                if (q == 0) {
                    v = fmaf(rv1[s],   w00, v);
                    v = fmaf(rv1[s-1], w02, v);
                    v = fmaf(rv2[s],   w20, v);
                    v = fmaf(rv2[s-1], w22, v);
                } else {
                    v = fmaf(rv1[s],   w01, v);
                    v = fmaf(rv1[s-1], w03, v);
                    v = fmaf(rv2[s],   w21, v);
                    v = fmaf(rv2[s-1], w23, v);
                }
                acc[i][j] = v;
            }
        }
    }
    #pragma unroll
    for (int i = 0; i < 4; i++) {
        int oc = ocg*4 + i;
        float bb = __ldg(b + oc);
        float* op = g_d2 + ((n*64 + oc)*128 + oh)*128 + ow0;
        #pragma unroll
        for (int j = 0; j < 32; j++) {
            float v = acc[i][j] + bb;
            op[j] = v > 0.f ? v : 0.f;
        }
    }
}

// ---------------- d3: convT 64->1, k4 s2 p1, 128->256, no ReLU (R5 form) ----------------
// block 64: tid&15 = owg (16 x 16), tid>>4 = ohg (4 x 4 rows); grid (16, N)
__global__ void __launch_bounds__(64) k_d3(const float* __restrict__ w,
                                           const float* __restrict__ b,
                                           float* __restrict__ out) {
    __shared__ float ws[1024];
    int tid = threadIdx.x;
    for (int t = tid; t < 1024; t += 64) ws[t] = w[t];
    __syncthreads();

    int owg = tid & 15, ohg = tid >> 4;
    int n = blockIdx.y;
    int ob = blockIdx.x*16 + ohg*4;
    int ow0 = owg*16;

    float acc[4][16];
    #pragma unroll
    for (int i = 0; i < 4; i++)
        #pragma unroll
        for (int j = 0; j < 16; j++) acc[i][j] = 0.f;

    int ihb = (ob >> 1) - 1;
    int iwb = (ow0 >> 1) - 1;
    const float* inn = g_d2 + n*(64*16384);

    for (int ic = 0; ic < 64; ic++) {
        const float* ip = inn + ic*16384;
        float rv[4][10];
        #pragma unroll
        for (int rr = 0; rr < 4; rr++) {
            int ih = ihb + rr;
            bool hok = (unsigned)ih < 128u;
            const float* row = ip + ih*128;
            #pragma unroll
            for (int t = 0; t < 10; t++) {
                int iw = iwb + t;
                rv[rr][t] = (hok && (unsigned)iw < 128u) ? __ldg(row + iw) : 0.f;
            }
        }
        float wr[16];
        #pragma unroll
        for (int t = 0; t < 16; t++) wr[t] = ws[ic*16 + t];

        #pragma unroll
        for (int rr = 0; rr < 4; rr++) {
            const int pp = (rr + 1) & 1;
            const int rel1 = ((rr + 1) >> 1) + 1;
            const int rel2 = rel1 - 1;
            #pragma unroll
            for (int j = 0; j < 16; j++) {
                const int q = (j + 1) & 1;
                const int s = ((j + 1) >> 1) + 1;
                float v = acc[rr][j];
                v = fmaf(rv[rel1][s],   wr[pp*4 + q],       v);
                v = fmaf(rv[rel1][s-1], wr[pp*4 + q + 2],   v);
                v = fmaf(rv[rel2][s],   wr[(pp+2)*4 + q],   v);
                v = fmaf(rv[rel2][s-1], wr[(pp+2)*4 + q+2], v);
                acc[rr][j] = v;
            }
        }
    }
    float bb = __ldg(b);
    #pragma unroll
    for (int rr = 0; rr < 4; rr++) {
        float* op = out + n*65536 + (ob + rr)*256 + ow0;
        #pragma unroll
        for (int j = 0; j < 16; j++) op[j] = acc[rr][j] + bb;
    }
}

// ---------------- launch ----------------
extern "C" void kernel_launch(void* const* d_in, const int* in_sizes, int n_in,
                              void* d_out, int out_size) {
    const float* x   = (const float*)d_in[0];
    const float* e1w = (const float*)d_in[1];  const float* e1b = (const float*)d_in[2];
    const float* e2w = (const float*)d_in[3];  const float* e2b = (const float*)d_in[4];
    const float* e3w = (const float*)d_in[5];  const float* e3b = (const float*)d_in[6];
    const float* emb = (const float*)d_in[7];
    const float* d1w = (const float*)d_in[8];  const float* d1b = (const float*)d_in[9];
    const float* d2w = (const float*)d_in[10]; const float* d2b = (const float*)d_in[11];
    const float* d3w = (const float*)d_in[12]; const float* d3b = (const float*)d_in[13];

    float* out  = (float*)d_out;
    float* xhat = out;                          // 64*1*256*256   = 4194304
    float* ze   = out + 4194304;                // 64*64*64*64    = 16777216
    float* zq   = out + 4194304 + 16777216;     // 64*64*64*64

    k_enorm<<<1, 512>>>(emb);
    k_e1<<<dim3(128, 4, NB), 128>>>(x, e1w, e1b);
    k_e2<<<dim3(8, 8, NB), 256>>>(e2w, e2b);
    k_e3<<<dim3(8, 8, NB), 256>>>(e3w, e3b, ze);
    k_vq<<<1024, 128>>>(ze, emb, zq);
    k_d1<<<dim3(4, NB, 4), 64>>>(zq, d1w, d1b);
    k_d2<<<dim3(8, NB, 16), 64>>>(d2w, d2b);
    k_d3<<<dim3(16, NB), 64>>>(d3w, d3b, xhat);
}